// round 4
// baseline (speedup 1.0000x reference)
#include <cuda_runtime.h>
#include <math.h>

#define NCOL 22
#define NEMB 12
#define D    64
#define B    2048
#define NPAIR 253   // 22 diagonal + 231 upper-triangle pairs

// ---------------- scratch (device globals: no allocation allowed) ------------
__device__ float  g_T[NCOL * NEMB * D];      // f(tables) table, 66 KB
__device__ float  g_n2[NCOL * NEMB];         // per-(col,emb) squared norm
__device__ float  g_colsq[NCOL];             // per-col sum of squared norms
__device__ float  g_L[NCOL * 2 * D];         // folded linear weights  [i][o][d]
__device__ float4 g_W2[NPAIR * D];           // {Wq0,Wq1,Wd0,Wd1} per (pair,d)

// ---------------- build T[i,e,d] = f(tables[i,e,d]) and n2[i,e] --------------
__global__ void k_build_T(const float* __restrict__ tables,
                          const float* __restrict__ w1, const float* __restrict__ b1,
                          const float* __restrict__ w2, const float* __restrict__ b2) {
    int ie = blockIdx.x;          // 0..NCOL*NEMB-1
    int d  = threadIdx.x;         // 0..63
    float x = tables[ie * D + d];
    float acc = b2[0];
#pragma unroll
    for (int h = 0; h < 8; h++) acc += w2[h] * tanhf(x * w1[h] + b1[h]);
    g_T[ie * D + d] = acc;

    float sq = x * x;
#pragma unroll
    for (int o = 16; o; o >>= 1) sq += __shfl_xor_sync(0xffffffffu, sq, o);
    __shared__ float s[2];
    if ((threadIdx.x & 31) == 0) s[threadIdx.x >> 5] = sq;
    __syncthreads();
    if (threadIdx.x == 0) g_n2[ie] = s[0] + s[1];
}

// ---------------- per-column squared norm via feature gather -----------------
__global__ void k_colsq(const int* __restrict__ features) {
    int i = blockIdx.x;
    float sum = 0.f;
    for (int b = threadIdx.x; b < B; b += blockDim.x)
        sum += g_n2[i * NEMB + features[i * B + b]];
#pragma unroll
    for (int o = 16; o; o >>= 1) sum += __shfl_xor_sync(0xffffffffu, sum, o);
    __shared__ float s[8];
    int w = threadIdx.x >> 5;
    if ((threadIdx.x & 31) == 0) s[w] = sum;
    __syncthreads();
    if (threadIdx.x == 0) {
        float t = 0.f;
        for (int k = 0; k < 8; k++) t += s[k];
        g_colsq[i] = t;
    }
}

__global__ void k_regs(float* __restrict__ out, int out_size) {
    int l = threadIdx.x;
    float v = (l < NCOL) ? sqrtf(g_colsq[l]) : 0.f;
#pragma unroll
    for (int o = 16; o; o >>= 1) v += __shfl_xor_sync(0xffffffffu, v, o);
    if (l == 0 && out_size > B * 2)
        out[B * 2] = 0.001f * (2.0f * NCOL) * v;
}

// ---------------- fold ALL linear terms into L[i,o,d] ------------------------
// out_plus + out_cat + the (t_i+t_j)/2 parts of out_max/out_min, arch_w scaled.
__global__ void k_build_L(const float* __restrict__ Wops,
                          const float* __restrict__ Wcat,
                          const float* __restrict__ aw) {
    int io = blockIdx.x;            // i*2+o
    int i = io >> 1, o = io & 1;
    int d = threadIdx.x;
    const int SZ = NCOL * NCOL * 2 * D;
    float sp = 0.f, smx = 0.f, smn = 0.f, sct = 0.f;
    for (int j = 0; j < NCOL; j++) {
        int ij = ((i * NCOL + j) * 2 + o) * D + d;
        int ji = ((j * NCOL + i) * 2 + o) * D + d;
        sp  += Wops[0 * SZ + ij] + Wops[0 * SZ + ji];
        smx += Wops[2 * SZ + ij] + Wops[2 * SZ + ji];
        smn += Wops[3 * SZ + ij] + Wops[3 * SZ + ji];
        sct += Wcat[((i * NCOL + j) * 2 + o) * (2 * D) + d]           // Wc1 row-sum
             + Wcat[((j * NCOL + i) * 2 + o) * (2 * D) + D + d];      // Wc2 col-sum
    }
    g_L[(i * 2 + o) * D + d] =
        aw[0] * sp + aw[4] * sct + 0.5f * (aw[2] * smx + aw[3] * smn);
}

// ---------------- symmetrized pairwise weights -------------------------------
// Wq = a1 * sym(Wm); Wd = 0.5 * (a2*sym(Wmax) - a3*sym(Wmin)); diag Wd=0.
__global__ void k_build_W2(const float* __restrict__ Wops,
                           const float* __restrict__ aw) {
    int ij = blockIdx.x;
    int i = ij / NCOL, j = ij % NCOL;
    if (j < i) return;
    int d = threadIdx.x;
    const int SZ = NCOL * NCOL * 2 * D;
    int p = i * NCOL - i * (i + 1) / 2 + j;
    int a0 = ((i * NCOL + j) * 2 + 0) * D + d;
    int a1 = ((i * NCOL + j) * 2 + 1) * D + d;
    int c0 = ((j * NCOL + i) * 2 + 0) * D + d;
    int c1 = ((j * NCOL + i) * 2 + 1) * D + d;
    float w1a = aw[1], w2a = aw[2], w3a = aw[3];
    float4 w;
    if (i == j) {
        w.x = w1a * Wops[SZ + a0];
        w.y = w1a * Wops[SZ + a1];
        w.z = 0.f;
        w.w = 0.f;
    } else {
        w.x = w1a * (Wops[SZ + a0] + Wops[SZ + c0]);
        w.y = w1a * (Wops[SZ + a1] + Wops[SZ + c1]);
        w.z = 0.5f * (w2a * (Wops[2 * SZ + a0] + Wops[2 * SZ + c0])
                    - w3a * (Wops[3 * SZ + a0] + Wops[3 * SZ + c0]));
        w.w = 0.5f * (w2a * (Wops[2 * SZ + a1] + Wops[2 * SZ + c1])
                    - w3a * (Wops[3 * SZ + a1] + Wops[3 * SZ + c1]));
    }
    g_W2[p * D + d] = w;
}

// ---------------- hot kernel: 2 batches / thread, d in lanes -----------------
__global__ void __launch_bounds__(512, 1)
k_main(const int* __restrict__ features, float* __restrict__ out) {
    int tid = threadIdx.x;
    int d = tid & 63;
    int g = tid >> 6;                         // 0..7
    int b0 = blockIdx.x * 16 + g * 2;

    float tA[NCOL], tB[NCOL];
#pragma unroll
    for (int i = 0; i < NCOL; i++) {
        int eA = __ldg(&features[i * B + b0]);
        int eB = __ldg(&features[i * B + b0 + 1]);
        tA[i] = g_T[(i * NEMB + eA) * D + d];
        tB[i] = g_T[(i * NEMB + eB) * D + d];
    }

    float a0A = 0.f, a1A = 0.f, a0B = 0.f, a1B = 0.f;
#pragma unroll
    for (int i = 0; i < NCOL; i++) {
        float L0 = g_L[(i * 2 + 0) * D + d];
        float L1 = g_L[(i * 2 + 1) * D + d];
        a0A = fmaf(tA[i], L0, a0A); a1A = fmaf(tA[i], L1, a1A);
        a0B = fmaf(tB[i], L0, a0B); a1B = fmaf(tB[i], L1, a1B);
    }

#pragma unroll
    for (int i = 0; i < NCOL; i++) {
#pragma unroll
        for (int j = i; j < NCOL; j++) {
            int p = i * NCOL - i * (i + 1) / 2 + j;       // constant-folded
            float4 w = g_W2[p * D + d];
            float mA = tA[i] * tA[j], aA = fabsf(tA[i] - tA[j]);
            float mB = tB[i] * tB[j], aB = fabsf(tB[i] - tB[j]);
            a0A = fmaf(w.x, mA, a0A); a1A = fmaf(w.y, mA, a1A);
            a0A = fmaf(w.z, aA, a0A); a1A = fmaf(w.w, aA, a1A);
            a0B = fmaf(w.x, mB, a0B); a1B = fmaf(w.y, mB, a1B);
            a0B = fmaf(w.z, aB, a0B); a1B = fmaf(w.w, aB, a1B);
        }
    }

    // reduce over d: 32 lanes in-warp, then pair of warps via SMEM
#pragma unroll
    for (int o = 16; o; o >>= 1) {
        a0A += __shfl_xor_sync(0xffffffffu, a0A, o);
        a1A += __shfl_xor_sync(0xffffffffu, a1A, o);
        a0B += __shfl_xor_sync(0xffffffffu, a0B, o);
        a1B += __shfl_xor_sync(0xffffffffu, a1B, o);
    }
    __shared__ float red[16][4];
    int w = tid >> 5;
    if ((tid & 31) == 0) {
        red[w][0] = a0A; red[w][1] = a1A; red[w][2] = a0B; red[w][3] = a1B;
    }
    __syncthreads();
    if (tid < 8) {
        int bb = blockIdx.x * 16 + tid * 2;
        out[bb * 2 + 0]       = red[2 * tid][0] + red[2 * tid + 1][0];
        out[bb * 2 + 1]       = red[2 * tid][1] + red[2 * tid + 1][1];
        out[(bb + 1) * 2 + 0] = red[2 * tid][2] + red[2 * tid + 1][2];
        out[(bb + 1) * 2 + 1] = red[2 * tid][3] + red[2 * tid + 1][3];
    }
}

// ---------------- launch -----------------------------------------------------
extern "C" void kernel_launch(void* const* d_in, const int* in_sizes, int n_in,
                              void* d_out, int out_size) {
    const int*   features = (const int*)  d_in[0];
    const float* tables   = (const float*)d_in[1];
    const float* w1       = (const float*)d_in[2];
    const float* b1       = (const float*)d_in[3];
    const float* w2       = (const float*)d_in[4];
    const float* b2       = (const float*)d_in[5];
    const float* Wops     = (const float*)d_in[6];
    const float* Wcat     = (const float*)d_in[7];
    const float* aw       = (const float*)d_in[8];
    float* out = (float*)d_out;

    k_build_T <<<NCOL * NEMB, 64>>>(tables, w1, b1, w2, b2);
    k_colsq   <<<NCOL, 256>>>(features);
    k_regs    <<<1, 32>>>(out, out_size);
    k_build_L <<<NCOL * 2, 64>>>(Wops, Wcat, aw);
    k_build_W2<<<NCOL * NCOL, 64>>>(Wops, aw);
    k_main    <<<B / 16, 512>>>(features, out);
}

// round 5
// speedup vs baseline: 1.6327x; 1.6327x over previous
#include <cuda_runtime.h>
#include <math.h>

#define NCOL 22
#define NEMB 12
#define D    64
#define B    2048
#define NPAIR 253           // 22 diag + 231 upper pairs
#define NE2  (NEMB*NEMB)    // 144

// ---------------- scratch (device globals; no allocation allowed) ------------
__device__ float  g_T[NCOL * NEMB * D];        // f(tables), 66 KB
__device__ float  g_colsq[NCOL];               // per-col sum of squared norms
__device__ float  g_L[NCOL * 2 * D];           // folded linear weights [i][o][d]
__device__ float4 g_W2[NPAIR * D];             // {wq0,wq1,wd0,wd1} per (pair,d)
__device__ float2 g_S[NPAIR * NE2];            // pairwise lookup table, 291 KB

// p -> (i,j) for upper-triangular-incl-diag enumeration
__device__ __forceinline__ void pair_ij(int p, int& i, int& j) {
    int ii = 0, rem = p;
    while (rem >= NCOL - ii) { rem -= NCOL - ii; ii++; }
    i = ii; j = ii + rem;
}

// ---------------- k_embed: T[i,e,d], n2, colsq — one block per column --------
__global__ void __launch_bounds__(768, 1)
k_embed(const float* __restrict__ tables, const int* __restrict__ features,
        const float* __restrict__ w1, const float* __restrict__ b1,
        const float* __restrict__ w2, const float* __restrict__ b2) {
    int i = blockIdx.x;           // column
    int t = threadIdx.x;          // 0..767  == e*64 + d
    __shared__ float s_warp[24];
    __shared__ float s_n2[NEMB];

    float x = tables[i * NEMB * D + t];
    float acc = b2[0];
#pragma unroll
    for (int h = 0; h < 8; h++) acc += w2[h] * tanhf(x * w1[h] + b1[h]);
    g_T[i * NEMB * D + t] = acc;

    // n2[e] = sum_d x^2 : warp-reduce (each e spans exactly 2 warps)
    float sq = x * x;
#pragma unroll
    for (int o = 16; o; o >>= 1) sq += __shfl_xor_sync(0xffffffffu, sq, o);
    if ((t & 31) == 0) s_warp[t >> 5] = sq;
    __syncthreads();
    if (t < NEMB) s_n2[t] = s_warp[2 * t] + s_warp[2 * t + 1];
    __syncthreads();

    // colsq[i] = sum_b n2[features[i,b]]
    float sum = 0.f;
    for (int b = t; b < B; b += 768)
        sum += s_n2[features[i * B + b]];
#pragma unroll
    for (int o = 16; o; o >>= 1) sum += __shfl_xor_sync(0xffffffffu, sum, o);
    if ((t & 31) == 0) s_warp[t >> 5] = sum;
    __syncthreads();
    if (t < 32) {
        float v = (t < 24) ? s_warp[t] : 0.f;
#pragma unroll
        for (int o = 16; o; o >>= 1) v += __shfl_xor_sync(0xffffffffu, v, o);
        if (t == 0) g_colsq[i] = v;
    }
}

// ---------------- k_wts: folded linear L (blocks 0..43) + sym pair W2 --------
__global__ void __launch_bounds__(256, 4)
k_wts(const float* __restrict__ Wops, const float* __restrict__ Wcat,
      const float* __restrict__ aw) {
    const int SZ = NCOL * NCOL * 2 * D;
    int bid = blockIdx.x, t = threadIdx.x;

    if (bid < NCOL * 2) {
        // L[i,o,d]: out_plus + out_cat + (t_i+t_j)/2 halves of max/min
        int i = bid >> 1, o = bid & 1;
        int d = t & 63, g = t >> 6;                 // 4 j-slices
        float sp = 0.f, smx = 0.f, smn = 0.f, sct = 0.f;
        for (int j = g; j < NCOL; j += 4) {
            int ij = ((i * NCOL + j) * 2 + o) * D + d;
            int ji = ((j * NCOL + i) * 2 + o) * D + d;
            sp  += Wops[ij]          + Wops[ji];
            smx += Wops[2 * SZ + ij] + Wops[2 * SZ + ji];
            smn += Wops[3 * SZ + ij] + Wops[3 * SZ + ji];
            sct += Wcat[((i * NCOL + j) * 2 + o) * (2 * D) + d]        // Wc1 row-sum
                 + Wcat[((j * NCOL + i) * 2 + o) * (2 * D) + D + d];   // Wc2 col-sum
        }
        __shared__ float4 s_red[4][64];
        s_red[g][d] = make_float4(sp, smx, smn, sct);
        __syncthreads();
        if (t < 64) {
            float4 a = s_red[0][t], b = s_red[1][t], c = s_red[2][t], e = s_red[3][t];
            float vsp = a.x + b.x + c.x + e.x;
            float vmx = a.y + b.y + c.y + e.y;
            float vmn = a.z + b.z + c.z + e.z;
            float vct = a.w + b.w + c.w + e.w;
            g_L[bid * D + t] = aw[0] * vsp + aw[4] * vct
                             + 0.5f * (aw[2] * vmx + aw[3] * vmn);
        }
    } else {
        // symmetrized pairwise weights
        int p = bid - NCOL * 2;
        int i, j; pair_ij(p, i, j);
        if (t < 64) {
            int d = t;
            int a0 = ((i * NCOL + j) * 2 + 0) * D + d;
            int a1 = ((i * NCOL + j) * 2 + 1) * D + d;
            int c0 = ((j * NCOL + i) * 2 + 0) * D + d;
            int c1 = ((j * NCOL + i) * 2 + 1) * D + d;
            float w1a = aw[1], w2a = aw[2], w3a = aw[3];
            float4 w;
            if (i == j) {
                w.x = w1a * Wops[SZ + a0];
                w.y = w1a * Wops[SZ + a1];
                w.z = 0.f;
                w.w = 0.f;
            } else {
                w.x = w1a * (Wops[SZ + a0] + Wops[SZ + c0]);
                w.y = w1a * (Wops[SZ + a1] + Wops[SZ + c1]);
                w.z = 0.5f * (w2a * (Wops[2 * SZ + a0] + Wops[2 * SZ + c0])
                            - w3a * (Wops[3 * SZ + a0] + Wops[3 * SZ + c0]));
                w.w = 0.5f * (w2a * (Wops[2 * SZ + a1] + Wops[2 * SZ + c1])
                            - w3a * (Wops[3 * SZ + a1] + Wops[3 * SZ + c1]));
            }
            g_W2[p * D + d] = w;
        }
    }
}

// ---------------- k_S: tabulate pairwise contributions per (pair,e1,e2) ------
// S[p][e1][e2] = { sum_d wq0*Ti*Tj + wd0*|Ti-Tj| , same with wq1/wd1 }
// Diagonal pairs additionally fold the linear term (only e1==e2 is ever read).
__global__ void __launch_bounds__(160, 8)
k_S() {
    int p = blockIdx.x;
    int i, j; pair_ij(p, i, j);
    int t = threadIdx.x;

    __shared__ float  sTi[NEMB][D + 1];
    __shared__ float  sTj[NEMB][D + 1];
    __shared__ float4 sW[D];
    __shared__ float  sL[2 * D];

    for (int idx = t; idx < NEMB * D; idx += 160) {
        int e = idx >> 6, d = idx & 63;
        sTi[e][d] = g_T[i * NEMB * D + idx];
        sTj[e][d] = g_T[j * NEMB * D + idx];
    }
    for (int idx = t; idx < D; idx += 160) sW[idx] = g_W2[p * D + idx];
    bool diag = (i == j);
    if (diag)
        for (int idx = t; idx < 2 * D; idx += 160) sL[idx] = g_L[i * 2 * D + idx];
    __syncthreads();

    if (t < NE2) {
        int e1 = t / NEMB, e2 = t % NEMB;
        bool dl = diag && (e1 == e2);
        float s0 = 0.f, s1 = 0.f, l0 = 0.f, l1 = 0.f;
#pragma unroll 4
        for (int d = 0; d < D; d++) {
            float4 w = sW[d];
            float ti = sTi[e1][d], tj = sTj[e2][d];
            float m = ti * tj;
            float a = fabsf(ti - tj);
            s0 = fmaf(w.x, m, fmaf(w.z, a, s0));
            s1 = fmaf(w.y, m, fmaf(w.w, a, s1));
            if (dl) { l0 = fmaf(ti, sL[d], l0); l1 = fmaf(ti, sL[D + d], l1); }
        }
        if (dl) { s0 += l0; s1 += l1; }
        g_S[p * NE2 + t] = make_float2(s0, s1);
    }
}

// ---------------- k_main: warp per batch, 253 table gathers ------------------
__global__ void __launch_bounds__(256, 4)
k_main(const int* __restrict__ features, float* __restrict__ out, int out_size) {
    __shared__ int s_feat[8][NCOL];
    int t = threadIdx.x;
    int b0 = blockIdx.x * 8;

    for (int idx = t; idx < 8 * NCOL; idx += 256) {
        int i = idx >> 3, w = idx & 7;
        s_feat[w][i] = features[i * B + b0 + w];       // coalesced 8-wide
    }
    __syncthreads();

    int w = t >> 5, lane = t & 31;
    int b = b0 + w;

    int p0 = lane * 8;                // contiguous chunk of pairs per lane
    int i, j; pair_ij(p0, i, j);

    float a0 = 0.f, a1 = 0.f;
#pragma unroll
    for (int k = 0; k < 8; k++) {
        int p = p0 + k;
        if (p < NPAIR) {
            int eA = s_feat[w][i], eB = s_feat[w][j];
            float2 s = g_S[p * NE2 + eA * NEMB + eB];
            a0 += s.x; a1 += s.y;
            j++; if (j == NCOL) { i++; j = i; }
        }
    }
#pragma unroll
    for (int o = 16; o; o >>= 1) {
        a0 += __shfl_xor_sync(0xffffffffu, a0, o);
        a1 += __shfl_xor_sync(0xffffffffu, a1, o);
    }
    if (lane == 0) { out[b * 2] = a0; out[b * 2 + 1] = a1; }

    // regularizer scalar (colsq ready from k_embed)
    if (blockIdx.x == 0 && t < 32 && out_size > 2 * B) {
        float v = (t < NCOL) ? sqrtf(g_colsq[t]) : 0.f;
#pragma unroll
        for (int o = 16; o; o >>= 1) v += __shfl_xor_sync(0xffffffffu, v, o);
        if (t == 0) out[2 * B] = 0.001f * (2.0f * NCOL) * v;
    }
}

// ---------------- launch -----------------------------------------------------
extern "C" void kernel_launch(void* const* d_in, const int* in_sizes, int n_in,
                              void* d_out, int out_size) {
    const int*   features = (const int*)  d_in[0];
    const float* tables   = (const float*)d_in[1];
    const float* w1       = (const float*)d_in[2];
    const float* b1       = (const float*)d_in[3];
    const float* w2       = (const float*)d_in[4];
    const float* b2       = (const float*)d_in[5];
    const float* Wops     = (const float*)d_in[6];
    const float* Wcat     = (const float*)d_in[7];
    const float* aw       = (const float*)d_in[8];
    float* out = (float*)d_out;

    k_embed<<<NCOL, 768>>>(tables, features, w1, b1, w2, b2);
    k_wts  <<<NCOL * 2 + NPAIR, 256>>>(Wops, Wcat, aw);
    k_S    <<<NPAIR, 160>>>();
    k_main <<<B / 8, 256>>>(features, out, out_size);
}

// round 6
// speedup vs baseline: 1.7615x; 1.0789x over previous
#include <cuda_runtime.h>
#include <math.h>

#define NCOL 22
#define NEMB 12
#define D    64
#define B    2048
#define NPAIR 253           // 22 diag + 231 upper pairs
#define NE2  (NEMB*NEMB)    // 144

// ---------------- scratch (device globals; no allocation allowed) ------------
__device__ float  g_T[NCOL * NEMB * D];        // f(tables), 66 KB
__device__ float  g_colsq[NCOL];               // per-col sum of squared norms
__device__ float  g_L[NCOL * 2 * D];           // folded linear weights [i][o][d]
__device__ float4 g_W2[NPAIR * D];             // {wq0,wq1,wd0,wd1} per (pair,d)
__device__ float2 g_S[NPAIR * NE2];            // pairwise lookup table, 291 KB

// p -> (i,j) for upper-triangular-incl-diag enumeration
__device__ __forceinline__ void pair_ij(int p, int& i, int& j) {
    int ii = 0, rem = p;
    while (rem >= NCOL - ii) { rem -= NCOL - ii; ii++; }
    i = ii; j = ii + rem;
}

// ---------------- k_pre: FUSED embed (blocks 0..21) + L (22..65) + W2 (66..318)
__global__ void __launch_bounds__(256, 4)
k_pre(const float* __restrict__ tables, const int* __restrict__ features,
      const float* __restrict__ w1, const float* __restrict__ b1,
      const float* __restrict__ w2, const float* __restrict__ b2,
      const float* __restrict__ Wops, const float* __restrict__ Wcat,
      const float* __restrict__ aw) {
    const int SZ = NCOL * NCOL * 2 * D;
    int bid = blockIdx.x, t = threadIdx.x;

    if (bid < NCOL) {
        // ---- embed: T[i,e,d] = f(tables), n2 per e, colsq per column ----
        int i = bid;
        __shared__ float s_warp[24];
        __shared__ float s_n2[NEMB];
#pragma unroll
        for (int c = 0; c < 3; c++) {                 // 3*256 = 768 = NEMB*D
            int idx = c * 256 + t;
            float x = tables[i * NEMB * D + idx];
            float acc = b2[0];
#pragma unroll
            for (int h = 0; h < 8; h++) acc += w2[h] * tanhf(x * w1[h] + b1[h]);
            g_T[i * NEMB * D + idx] = acc;
            float sq = x * x;
#pragma unroll
            for (int o = 16; o; o >>= 1) sq += __shfl_xor_sync(0xffffffffu, sq, o);
            if ((t & 31) == 0) s_warp[idx >> 5] = sq;   // 24 half-e partials
            __syncthreads();
        }
        if (t < NEMB) s_n2[t] = s_warp[2 * t] + s_warp[2 * t + 1];
        __syncthreads();
        float sum = 0.f;
        for (int b = t; b < B; b += 256)
            sum += s_n2[features[i * B + b]];
#pragma unroll
        for (int o = 16; o; o >>= 1) sum += __shfl_xor_sync(0xffffffffu, sum, o);
        if ((t & 31) == 0) s_warp[t >> 5] = sum;
        __syncthreads();
        if (t == 0) {
            float v = 0.f;
            for (int k = 0; k < 8; k++) v += s_warp[k];
            g_colsq[i] = v;
        }
    } else if (bid < NCOL + NCOL * 2) {
        // ---- L[i,o,d]: out_plus + out_cat + (t_i+t_j)/2 halves of max/min ----
        int lb = bid - NCOL;
        int i = lb >> 1, o = lb & 1;
        int d = t & 63, g = t >> 6;                    // 4 j-slices
        float sp = 0.f, smx = 0.f, smn = 0.f, sct = 0.f;
        for (int j = g; j < NCOL; j += 4) {
            int ij = ((i * NCOL + j) * 2 + o) * D + d;
            int ji = ((j * NCOL + i) * 2 + o) * D + d;
            sp  += Wops[ij]          + Wops[ji];
            smx += Wops[2 * SZ + ij] + Wops[2 * SZ + ji];
            smn += Wops[3 * SZ + ij] + Wops[3 * SZ + ji];
            sct += Wcat[((i * NCOL + j) * 2 + o) * (2 * D) + d]        // Wc1 row-sum
                 + Wcat[((j * NCOL + i) * 2 + o) * (2 * D) + D + d];   // Wc2 col-sum
        }
        __shared__ float4 s_red[4][64];
        s_red[g][d] = make_float4(sp, smx, smn, sct);
        __syncthreads();
        if (t < 64) {
            float4 a = s_red[0][t], b = s_red[1][t], c = s_red[2][t], e = s_red[3][t];
            g_L[lb * D + t] = aw[0] * (a.x + b.x + c.x + e.x)
                            + aw[4] * (a.w + b.w + c.w + e.w)
                            + 0.5f * (aw[2] * (a.y + b.y + c.y + e.y)
                                    + aw[3] * (a.z + b.z + c.z + e.z));
        }
    } else {
        // ---- symmetrized pairwise weights W2[p][d] ----
        int p = bid - 3 * NCOL;
        int i, j; pair_ij(p, i, j);
        if (t < 64) {
            int d = t;
            int a0 = ((i * NCOL + j) * 2 + 0) * D + d;
            int a1 = ((i * NCOL + j) * 2 + 1) * D + d;
            int c0 = ((j * NCOL + i) * 2 + 0) * D + d;
            int c1 = ((j * NCOL + i) * 2 + 1) * D + d;
            float w1a = aw[1], w2a = aw[2], w3a = aw[3];
            float4 w;
            if (i == j) {
                w.x = w1a * Wops[SZ + a0];
                w.y = w1a * Wops[SZ + a1];
                w.z = 0.f;
                w.w = 0.f;
            } else {
                w.x = w1a * (Wops[SZ + a0] + Wops[SZ + c0]);
                w.y = w1a * (Wops[SZ + a1] + Wops[SZ + c1]);
                w.z = 0.5f * (w2a * (Wops[2 * SZ + a0] + Wops[2 * SZ + c0])
                            - w3a * (Wops[3 * SZ + a0] + Wops[3 * SZ + c0]));
                w.w = 0.5f * (w2a * (Wops[2 * SZ + a1] + Wops[2 * SZ + c1])
                            - w3a * (Wops[3 * SZ + a1] + Wops[3 * SZ + c1]));
            }
            g_W2[p * D + d] = w;
        }
    }
}

// ---------------- k_S: tabulate pairwise contributions per (pair,e1,e2) ------
// S[p][e1][e2] = { sum_d wq0*Ti*Tj + wd0*|Ti-Tj| , same with wq1/wd1 }
// Diagonal pairs additionally fold the linear term (only e1==e2 is ever read).
__global__ void __launch_bounds__(160, 8)
k_S() {
    int p = blockIdx.x;
    int i, j; pair_ij(p, i, j);
    int t = threadIdx.x;

    __shared__ float  sTi[NEMB][D + 1];
    __shared__ float  sTj[NEMB][D + 1];
    __shared__ float4 sW[D];
    __shared__ float  sL[2 * D];

    for (int idx = t; idx < NEMB * D; idx += 160) {
        int e = idx >> 6, d = idx & 63;
        sTi[e][d] = g_T[i * NEMB * D + idx];
        sTj[e][d] = g_T[j * NEMB * D + idx];
    }
    for (int idx = t; idx < D; idx += 160) sW[idx] = g_W2[p * D + idx];
    bool diag = (i == j);
    if (diag)
        for (int idx = t; idx < 2 * D; idx += 160) sL[idx] = g_L[i * 2 * D + idx];
    __syncthreads();

    if (t < NE2) {
        int e1 = t / NEMB, e2 = t % NEMB;
        bool dl = diag && (e1 == e2);
        float s0 = 0.f, s1 = 0.f, l0 = 0.f, l1 = 0.f;
#pragma unroll 4
        for (int d = 0; d < D; d++) {
            float4 w = sW[d];
            float ti = sTi[e1][d], tj = sTj[e2][d];
            float m = ti * tj;
            float a = fabsf(ti - tj);
            s0 = fmaf(w.x, m, fmaf(w.z, a, s0));
            s1 = fmaf(w.y, m, fmaf(w.w, a, s1));
            if (dl) { l0 = fmaf(ti, sL[d], l0); l1 = fmaf(ti, sL[D + d], l1); }
        }
        if (dl) { s0 += l0; s1 += l1; }
        g_S[p * NE2 + t] = make_float2(s0, s1);
    }
}

// ---------------- k_main: 2 warps per batch, 4 gathers/lane ------------------
__global__ void __launch_bounds__(256, 8)
k_main(const int* __restrict__ features, float* __restrict__ out, int out_size) {
    __shared__ int   s_feat[4][NCOL];
    __shared__ float s_red[8][2];
    int t = threadIdx.x;
    int b0 = blockIdx.x * 4;

    for (int idx = t; idx < 4 * NCOL; idx += 256) {
        int i = idx >> 2, w = idx & 3;
        s_feat[w][i] = features[i * B + b0 + w];
    }
    __syncthreads();

    int w = t >> 5, lane = t & 31;
    int bl = w >> 1;                     // batch within block, 0..3
    int slot = ((w & 1) << 5) | lane;    // 0..63
    const int* feat = s_feat[bl];

    int p0 = slot * 4;
    int i, j; pair_ij(p0, i, j);

    float a0 = 0.f, a1 = 0.f;
#pragma unroll
    for (int k = 0; k < 4; k++) {
        int p = p0 + k;
        if (p < NPAIR) {
            float2 s = __ldg(&g_S[p * NE2 + feat[i] * NEMB + feat[j]]);
            a0 += s.x; a1 += s.y;
            j++; if (j == NCOL) { i++; j = i; }
        }
    }
#pragma unroll
    for (int o = 16; o; o >>= 1) {
        a0 += __shfl_xor_sync(0xffffffffu, a0, o);
        a1 += __shfl_xor_sync(0xffffffffu, a1, o);
    }
    if (lane == 0) { s_red[w][0] = a0; s_red[w][1] = a1; }
    __syncthreads();
    if (t < 4) {
        int b = b0 + t;
        out[b * 2]     = s_red[2 * t][0] + s_red[2 * t + 1][0];
        out[b * 2 + 1] = s_red[2 * t][1] + s_red[2 * t + 1][1];
    }

    // regularizer scalar (colsq ready from k_pre)
    if (blockIdx.x == 0 && t >= 32 && t < 64 && out_size > 2 * B) {
        int l = t - 32;
        float v = (l < NCOL) ? sqrtf(g_colsq[l]) : 0.f;
#pragma unroll
        for (int o = 16; o; o >>= 1) v += __shfl_xor_sync(0xffffffffu, v, o);
        if (l == 0) out[2 * B] = 0.001f * (2.0f * NCOL) * v;
    }
}

// ---------------- launch -----------------------------------------------------
extern "C" void kernel_launch(void* const* d_in, const int* in_sizes, int n_in,
                              void* d_out, int out_size) {
    const int*   features = (const int*)  d_in[0];
    const float* tables   = (const float*)d_in[1];
    const float* w1       = (const float*)d_in[2];
    const float* b1       = (const float*)d_in[3];
    const float* w2       = (const float*)d_in[4];
    const float* b2       = (const float*)d_in[5];
    const float* Wops     = (const float*)d_in[6];
    const float* Wcat     = (const float*)d_in[7];
    const float* aw       = (const float*)d_in[8];
    float* out = (float*)d_out;

    k_pre  <<<NCOL + NCOL * 2 + NPAIR, 256>>>(tables, features, w1, b1, w2, b2,
                                              Wops, Wcat, aw);
    k_S    <<<NPAIR, 160>>>();
    k_main <<<B / 4, 256>>>(features, out, out_size);
}